// round 15
// baseline (speedup 1.0000x reference)
#include <cuda_runtime.h>
#include <cstdint>

// ---------------- scratch (static device globals; no allocation) ----------------
__device__ float d_h1[8 * 256 * 1024];      // after dup conv  (8MB)
__device__ float d_h2[8 * 64 * 2048];       // after c1 conv   (4MB)
__device__ float d_xx[8 * 2048];            // per-point squared norms
__device__ float d_g1[8 * 64];              // global max feature (int-atomic bits)
__device__ float d_local[8 * 64 * 2048];    // max over k        (4MB)
__device__ float d_W4a_t[64 * 256];         // W4a[:,0:64] transposed [k][o]
__device__ float d_wpack[4 * 4096];         // packed conv weights (for const copy)
// symmetric-pairwise partial top-4: [b][rowblk][otherblk][row128][4]
__device__ float d_pv[8 * 16 * 16 * 128 * 4];   // 8MB
__device__ int   d_pi[8 * 16 * 16 * 128 * 4];   // 8MB

// conv weights in constant memory: [0]=W2a_nb_t [4096]=W2a_diff_t
// [8192]=W2b_t [12288]=W2c_t   (all [c][o] layout, 64x64)
__constant__ float c_w[4 * 4096];

// ---------------- weight repack + g1 reset ----------------
__global__ void prep_weights(const float* __restrict__ W4a,
                             const float* __restrict__ W2a,
                             const float* __restrict__ W2b,
                             const float* __restrict__ W2c)
{
    int t = blockIdx.x * blockDim.x + threadIdx.x;
    if (t < 16384) {
        int k = t >> 8, o = t & 255;
        d_W4a_t[t] = W4a[o * 192 + k];
    } else if (t < 20480) {
        int i = t - 16384;
        int c = i >> 6, o = i & 63;
        float w0 = W2a[o * 128 + c];
        d_wpack[i]        = w0;                                  // W2a_nb_t
        d_wpack[4096 + i] = W2a[o * 128 + 64 + c] - w0;          // W2a_diff_t
    } else if (t < 24576) {
        int i = t - 20480;
        int c = i >> 6, o = i & 63;
        d_wpack[8192 + i] = W2b[o * 64 + c];                     // W2b_t
    } else if (t < 28672) {
        int i = t - 24576;
        int c = i >> 6, o = i & 63;
        d_wpack[12288 + i] = W2c[o * 64 + c];                    // W2c_t
    } else if (t < 29184) {
        d_g1[t - 28672] = 0.0f;
    }
}

// =====================================================================
// GEMM A: 128(O) x 128(N) tile, 256 threads, 8x8 micro-tile, Ktile 16.
// =====================================================================
__global__ void __launch_bounds__(256) gemmA(
    const float* __restrict__ A, const float* __restrict__ B, float* __restrict__ C,
    const float* __restrict__ scale, const float* __restrict__ bias,
    int K, int N, long sB, long sC)
{
    __shared__ float As[16][128];
    __shared__ float Bs[16][128];
    const float* Bp = B + (long)blockIdx.z * sB;
    float* Cp = C + (long)blockIdx.z * sC;
    const int o0 = blockIdx.y * 128;
    const int n0 = blockIdx.x * 128;
    const int tid = threadIdx.x;
    const int tx = tid & 15, ty = tid >> 4;

    const int ar = tid >> 1;
    const int aq = (tid & 1) * 8;
    const int bk = tid >> 4;
    const int bn = (tid & 15) * 8;

    float acc[8][8];
#pragma unroll
    for (int i = 0; i < 8; ++i)
#pragma unroll
        for (int j = 0; j < 8; ++j) acc[i][j] = 0.f;

    for (int k0 = 0; k0 < K; k0 += 16) {
        float4 a0 = *(const float4*)&A[(long)(o0 + ar) * K + k0 + aq];
        float4 a1 = *(const float4*)&A[(long)(o0 + ar) * K + k0 + aq + 4];
        As[aq + 0][ar] = a0.x; As[aq + 1][ar] = a0.y;
        As[aq + 2][ar] = a0.z; As[aq + 3][ar] = a0.w;
        As[aq + 4][ar] = a1.x; As[aq + 5][ar] = a1.y;
        As[aq + 6][ar] = a1.z; As[aq + 7][ar] = a1.w;
        *(float4*)&Bs[bk][bn]     = *(const float4*)&Bp[(long)(k0 + bk) * N + n0 + bn];
        *(float4*)&Bs[bk][bn + 4] = *(const float4*)&Bp[(long)(k0 + bk) * N + n0 + bn + 4];
        __syncthreads();
#pragma unroll 4
        for (int k = 0; k < 16; ++k) {
            float a[8], b[8];
            *(float4*)&a[0] = *(const float4*)&As[k][ty * 8];
            *(float4*)&a[4] = *(const float4*)&As[k][ty * 8 + 4];
            *(float4*)&b[0] = *(const float4*)&Bs[k][tx * 8];
            *(float4*)&b[4] = *(const float4*)&Bs[k][tx * 8 + 4];
#pragma unroll
            for (int i = 0; i < 8; ++i)
#pragma unroll
                for (int j = 0; j < 8; ++j)
                    acc[i][j] = fmaf(a[i], b[j], acc[i][j]);
        }
        __syncthreads();
    }

#pragma unroll
    for (int i = 0; i < 8; ++i) {
        int o = o0 + ty * 8 + i;
        float sv = scale[o];
        float bv = bias[o];
        float r[8];
#pragma unroll
        for (int j = 0; j < 8; ++j)
            r[j] = fmaxf(fmaf(acc[i][j], sv, bv), 0.f);
        *(float4*)&Cp[(long)o * N + n0 + tx * 8]     = *(float4*)&r[0];
        *(float4*)&Cp[(long)o * N + n0 + tx * 8 + 4] = *(float4*)&r[4];
    }
}

// =====================================================================
// GEMM L2: 64(O) x 128(N) tile, 256 threads, 8x4 micro-tile, Ktile 16.
// grid (16,1,8) = 128 CTAs. Fused xx + gmax.
// =====================================================================
__global__ void __launch_bounds__(256) gemmL2(
    const float* __restrict__ A, const float* __restrict__ B, float* __restrict__ C,
    const float* __restrict__ scale, const float* __restrict__ bias,
    int K, int N, long sB, long sC)
{
    __shared__ float As[16][64];
    __shared__ float Bs[16][128];
    __shared__ float ps[8 * 128];      // xx partials [ty][col]
    __shared__ float pm[64 * 32];      // gmax partials [o][tx]
    const int b = blockIdx.z;
    const float* Bp = B + (long)b * sB;
    float* Cp = C + (long)b * sC;
    const int n0 = blockIdx.x * 128;
    const int tid = threadIdx.x;
    const int tx = tid & 31, ty = tid >> 5;

    const int ar = tid >> 2;
    const int aq = (tid & 3) * 4;
    const int bk = tid >> 4;
    const int bn = (tid & 15) * 8;

    float acc[8][4];
#pragma unroll
    for (int i = 0; i < 8; ++i)
#pragma unroll
        for (int j = 0; j < 4; ++j) acc[i][j] = 0.f;

    for (int k0 = 0; k0 < K; k0 += 16) {
        float4 a0 = *(const float4*)&A[(long)ar * K + k0 + aq];
        As[aq + 0][ar] = a0.x; As[aq + 1][ar] = a0.y;
        As[aq + 2][ar] = a0.z; As[aq + 3][ar] = a0.w;
        *(float4*)&Bs[bk][bn]     = *(const float4*)&Bp[(long)(k0 + bk) * N + n0 + bn];
        *(float4*)&Bs[bk][bn + 4] = *(const float4*)&Bp[(long)(k0 + bk) * N + n0 + bn + 4];
        __syncthreads();
#pragma unroll 4
        for (int k = 0; k < 16; ++k) {
            float a[8], bb[4];
            *(float4*)&a[0] = *(const float4*)&As[k][ty * 8];
            *(float4*)&a[4] = *(const float4*)&As[k][ty * 8 + 4];
            *(float4*)&bb[0] = *(const float4*)&Bs[k][tx * 4];
#pragma unroll
            for (int i = 0; i < 8; ++i)
#pragma unroll
                for (int j = 0; j < 4; ++j)
                    acc[i][j] = fmaf(a[i], bb[j], acc[i][j]);
        }
        __syncthreads();
    }

    float px[4];
#pragma unroll
    for (int j = 0; j < 4; ++j) px[j] = 0.f;

#pragma unroll
    for (int i = 0; i < 8; ++i) {
        int o = ty * 8 + i;
        float sv = scale[o];
        float bv = bias[o];
        float r[4];
        float gm = 0.f;
#pragma unroll
        for (int j = 0; j < 4; ++j) {
            r[j] = fmaxf(fmaf(acc[i][j], sv, bv), 0.f);
            px[j] = fmaf(r[j], r[j], px[j]);
            gm = fmaxf(gm, r[j]);
        }
        pm[o * 32 + tx] = gm;
        *(float4*)&Cp[(long)o * N + n0 + tx * 4] = *(float4*)&r[0];
    }
#pragma unroll
    for (int j = 0; j < 4; ++j)
        ps[ty * 128 + tx * 4 + j] = px[j];
    __syncthreads();

    if (tid < 128) {
        float s = 0.f;
#pragma unroll
        for (int t = 0; t < 8; ++t) s += ps[t * 128 + tid];
        d_xx[b * 2048 + n0 + tid] = s;
    }
    if (tid < 64) {
        float m = 0.f;
#pragma unroll
        for (int t = 0; t < 32; ++t) m = fmaxf(m, pm[tid * 32 + t]);
        atomicMax((int*)&d_g1[b * 64 + tid], __float_as_int(m));
    }
}

// ---------------- top-4 inserts ----------------
__device__ __forceinline__ void ins4(float v, int m, float* V, int* I)
{
#pragma unroll
    for (int s = 0; s < 4; ++s) {
        if (v > V[s]) {
            float tv = V[s]; V[s] = v; v = tv;
            int   tm = I[s]; I[s] = m; m = tm;
        }
    }
}
__device__ __forceinline__ void ins4t(float v, int m, float* V, int* I)
{
#pragma unroll
    for (int s = 0; s < 4; ++s) {
        bool better = (v > V[s]) || (v == V[s] && m < I[s]);
        if (better) {
            float tv = V[s]; V[s] = v; v = tv;
            int   tm = I[s]; I[s] = m; m = tm;
        }
    }
}

// =====================================================================
// symmetric pairwise (R12-proven, measured 104 us). grid (136,8), 256 thr.
// =====================================================================
__global__ void __launch_bounds__(256) sym_pair()
{
    extern __shared__ float sm[];
    float* smI   = sm;                 // [64][128] phase 1
    float* smJ   = sm + 8192;          // [64][128] phase 1
    float* score = sm;                 // [128][129] phase 2 (aliases operands)
    float* sxxI  = sm + 16512;         // [128]
    float* sxxJ  = sm + 16640;         // [128]

    int I = 0, J = 0;
    {
        int rem = blockIdx.x;
#pragma unroll
        for (int i = 0; i < 16; ++i) {
            int cnt = 16 - i;
            if (rem < cnt) { I = i; J = i + rem; break; }
            rem -= cnt;
        }
    }
    const int b = blockIdx.y;
    const int tid = threadIdx.x;
    const int nI = I * 128, nJ = J * 128;
    const float* h = d_h2 + (long)b * 64 * 2048;

    for (int idx = tid; idx < 2048; idx += 256) {
        int c = idx >> 5, q4 = (idx & 31) * 4;
        *(float4*)&smI[c * 128 + q4] = *(const float4*)&h[c * 2048 + nI + q4];
        *(float4*)&smJ[c * 128 + q4] = *(const float4*)&h[c * 2048 + nJ + q4];
    }
    if (tid < 128) {
        sxxI[tid] = d_xx[b * 2048 + nI + tid];
        sxxJ[tid] = d_xx[b * 2048 + nJ + tid];
    }
    __syncthreads();

    const int tx = tid & 15, ty = tid >> 4;
    float acc[8][8];
#pragma unroll
    for (int i = 0; i < 8; ++i)
#pragma unroll
        for (int j = 0; j < 8; ++j) acc[i][j] = 0.f;

#pragma unroll 4
    for (int k = 0; k < 64; ++k) {
        float a[8], bb[8];
        *(float4*)&a[0] = *(const float4*)&smI[k * 128 + ty * 8];
        *(float4*)&a[4] = *(const float4*)&smI[k * 128 + ty * 8 + 4];
        *(float4*)&bb[0] = *(const float4*)&smJ[k * 128 + tx * 8];
        *(float4*)&bb[4] = *(const float4*)&smJ[k * 128 + tx * 8 + 4];
#pragma unroll
        for (int i = 0; i < 8; ++i)
#pragma unroll
            for (int j = 0; j < 8; ++j)
                acc[i][j] = fmaf(a[i], bb[j], acc[i][j]);
    }
    __syncthreads();   // operands dead; score may overwrite

#pragma unroll
    for (int i = 0; i < 8; ++i)
#pragma unroll
        for (int j = 0; j < 8; ++j)
            score[(ty * 8 + i) * 129 + tx * 8 + j] = acc[i][j];
    __syncthreads();

    if (tid < 128) {
        float V[4] = {-1e30f, -1e30f, -1e30f, -1e30f};
        int   Ix[4] = {0, 0, 0, 0};
        const float* srow = &score[tid * 129];
#pragma unroll 4
        for (int m = 0; m < 128; ++m) {
            float s = fmaf(2.0f, srow[m], -sxxJ[m]);
            if (s > V[3]) ins4(s, nJ + m, V, Ix);
        }
        long base = ((((long)b * 16 + I) * 16 + J) * 128 + tid) * 4;
        *(float4*)&d_pv[base] = make_float4(V[0], V[1], V[2], V[3]);
        *(int4*)&d_pi[base] = make_int4(Ix[0], Ix[1], Ix[2], Ix[3]);
    } else if (I < J) {
        int m = tid - 128;
        float V[4] = {-1e30f, -1e30f, -1e30f, -1e30f};
        int   Ix[4] = {0, 0, 0, 0};
#pragma unroll 4
        for (int rr = 0; rr < 128; ++rr) {
            float s = fmaf(2.0f, score[rr * 129 + m], -sxxI[rr]);
            if (s > V[3]) ins4(s, nI + rr, V, Ix);
        }
        long base = ((((long)b * 16 + J) * 16 + I) * 128 + m) * 4;
        *(float4*)&d_pv[base] = make_float4(V[0], V[1], V[2], V[3]);
        *(int4*)&d_pi[base] = make_int4(Ix[0], Ix[1], Ix[2], Ix[3]);
    }
}

// =====================================================================
// mega-fused edge convs v2: weights from __constant__ (LDC broadcast),
// smem 74.2KB -> 3 CTAs/SM (24 warps, was 16). Phases: merge+ctr ->
// gather -> GEMM1(+diff) -> GEMM2 -> GEMM3(+kmax). grid (64,8), 256 thr.
// smem floats: ping 8192 | pong 8192 | ctr 2048 | sidx 128 = 18560
// =====================================================================
__global__ void __launch_bounds__(256, 3) megaconv(
    const float* __restrict__ s2a, const float* __restrict__ b2a,
    const float* __restrict__ s2b, const float* __restrict__ b2b,
    const float* __restrict__ s2c, const float* __restrict__ b2c)
{
    extern __shared__ float sm[];
    float* ping  = sm;
    float* pong  = sm + 8192;
    float* ctr   = sm + 16384;
    int*   sidx  = (int*)(sm + 18432);

    const int b = blockIdx.y;
    const int n0p = blockIdx.x * 32;
    const int tid = threadIdx.x;
    const int tx = tid & 31, ty = tid >> 5;
    const float* h = d_h2 + (long)b * 64 * 2048;

    if (tid < 32) {
        int row = n0p + tid;
        int rb = row >> 7, rl = row & 127;
        long pbase = ((((long)b * 16 + rb) * 16) * 128 + rl) * 4;
        float V[4] = {-1e30f, -1e30f, -1e30f, -1e30f};
        int   I[4] = {0, 0, 0, 0};
#pragma unroll
        for (int o = 0; o < 16; ++o) {
            float4 v = *(const float4*)&d_pv[pbase + (long)o * 512];
            int4  ix = *(const int4*)&d_pi[pbase + (long)o * 512];
            ins4t(v.x, ix.x, V, I);
            ins4t(v.y, ix.y, V, I);
            ins4t(v.z, ix.z, V, I);
            ins4t(v.w, ix.w, V, I);
        }
        sidx[tid * 4 + 0] = I[0];
        sidx[tid * 4 + 1] = I[1];
        sidx[tid * 4 + 2] = I[2];
        sidx[tid * 4 + 3] = I[3];
    } else {
        int t = tid - 32;
        for (int i = t; i < 512; i += 224) {
            int c = i >> 3, q4 = (i & 7) * 4;
            *(float4*)&ctr[c * 32 + q4] = *(const float4*)&h[c * 2048 + n0p + q4];
        }
    }
    __syncthreads();

#pragma unroll 4
    for (int e = tid; e < 8192; e += 256) {
        int c = e >> 7, j = e & 127;
        ping[e] = h[c * 2048 + sidx[j]];
    }
    __syncthreads();

    float acc[8][4];

    // ---- GEMM1: W2a_nb (c_w[0]) @ feat (+ diff term c_w[4096]) -> pong ----
#pragma unroll
    for (int i = 0; i < 8; ++i)
#pragma unroll
        for (int j = 0; j < 4; ++j) acc[i][j] = 0.f;
#pragma unroll 4
    for (int k = 0; k < 64; ++k) {
        float a[8], bb[4];
        *(float4*)&a[0] = *(const float4*)&c_w[k * 64 + ty * 8];
        *(float4*)&a[4] = *(const float4*)&c_w[k * 64 + ty * 8 + 4];
        *(float4*)&bb[0] = *(const float4*)&ping[k * 128 + tx * 4];
#pragma unroll
        for (int i = 0; i < 8; ++i)
#pragma unroll
            for (int j = 0; j < 4; ++j)
                acc[i][j] = fmaf(a[i], bb[j], acc[i][j]);
    }
    {
        float diffv[8];
#pragma unroll
        for (int i = 0; i < 8; ++i) diffv[i] = 0.f;
#pragma unroll 4
        for (int c = 0; c < 64; ++c) {
            float a[8];
            *(float4*)&a[0] = *(const float4*)&c_w[4096 + c * 64 + ty * 8];
            *(float4*)&a[4] = *(const float4*)&c_w[4096 + c * 64 + ty * 8 + 4];
            float cv = ctr[c * 32 + tx];
#pragma unroll
            for (int i = 0; i < 8; ++i)
                diffv[i] = fmaf(a[i], cv, diffv[i]);
        }
#pragma unroll
        for (int i = 0; i < 8; ++i) {
            int o = ty * 8 + i;
            float sv = s2a[o], bv = b2a[o];
            float r[4];
#pragma unroll
            for (int j = 0; j < 4; ++j)
                r[j] = fmaxf(fmaf(acc[i][j] + diffv[i], sv, bv), 0.f);
            *(float4*)&pong[o * 128 + tx * 4] = *(float4*)&r[0];
        }
    }
    __syncthreads();

    // ---- GEMM2: W2b (c_w[8192]) @ fa -> ping ----
#pragma unroll
    for (int i = 0; i < 8; ++i)
#pragma unroll
        for (int j = 0; j < 4; ++j) acc[i][j] = 0.f;
#pragma unroll 4
    for (int k = 0; k < 64; ++k) {
        float a[8], bb[4];
        *(float4*)&a[0] = *(const float4*)&c_w[8192 + k * 64 + ty * 8];
        *(float4*)&a[4] = *(const float4*)&c_w[8192 + k * 64 + ty * 8 + 4];
        *(float4*)&bb[0] = *(const float4*)&pong[k * 128 + tx * 4];
#pragma unroll
        for (int i = 0; i < 8; ++i)
#pragma unroll
            for (int j = 0; j < 4; ++j)
                acc[i][j] = fmaf(a[i], bb[j], acc[i][j]);
    }
#pragma unroll
    for (int i = 0; i < 8; ++i) {
        int o = ty * 8 + i;
        float sv = s2b[o], bv = b2b[o];
        float r[4];
#pragma unroll
        for (int j = 0; j < 4; ++j)
            r[j] = fmaxf(fmaf(acc[i][j], sv, bv), 0.f);
        *(float4*)&ping[o * 128 + tx * 4] = *(float4*)&r[0];
    }
    __syncthreads();

    // ---- GEMM3: W2c (c_w[12288]) @ fb -> kmax -> d_local ----
#pragma unroll
    for (int i = 0; i < 8; ++i)
#pragma unroll
        for (int j = 0; j < 4; ++j) acc[i][j] = 0.f;
#pragma unroll 4
    for (int k = 0; k < 64; ++k) {
        float a[8], bb[4];
        *(float4*)&a[0] = *(const float4*)&c_w[12288 + k * 64 + ty * 8];
        *(float4*)&a[4] = *(const float4*)&c_w[12288 + k * 64 + ty * 8 + 4];
        *(float4*)&bb[0] = *(const float4*)&ping[k * 128 + tx * 4];
#pragma unroll
        for (int i = 0; i < 8; ++i)
#pragma unroll
            for (int j = 0; j < 4; ++j)
                acc[i][j] = fmaf(a[i], bb[j], acc[i][j]);
    }
    float* locp = d_local + (long)b * 64 * 2048;
#pragma unroll
    for (int i = 0; i < 8; ++i) {
        int o = ty * 8 + i;
        float sv = s2c[o], bv = b2c[o];
        float r[4];
#pragma unroll
        for (int j = 0; j < 4; ++j)
            r[j] = fmaxf(fmaf(acc[i][j], sv, bv), 0.f);
        locp[(long)o * 2048 + n0p + tx] =
            fmaxf(fmaxf(r[0], r[1]), fmaxf(r[2], r[3]));
    }
}

// =====================================================================
// fused head: inline gpath (g1->g2->gb), h4 = relu(W4a_c@local + gb),
// out = W4b @ h4 + bias4b.  grid (16, 8), block 256.
// =====================================================================
__global__ void __launch_bounds__(256) head_out(
    const float* __restrict__ W3a, const float* __restrict__ s3a,
    const float* __restrict__ b3a, const float* __restrict__ W3b,
    const float* __restrict__ s3b, const float* __restrict__ b3b,
    const float* __restrict__ W4a, const float* __restrict__ bias4a,
    const float* __restrict__ W4b, const float* __restrict__ bias4b,
    float* __restrict__ out)
{
    extern __shared__ float smem[];
    float* As   = smem;                 // [64][256]
    float* Bs   = As + 64 * 256;        // [64][128]
    float* po   = Bs + 64 * 128;        // [16][3][128]
    float* sgb  = po + 16 * 3 * 128;    // [256]
    float* sw   = sgb + 256;            // [3][256]
    float* gin  = sw + 768;             // [64]
    float* gmid = gin + 64;             // [128]
    float* g2s  = gmid + 128;           // [128]

    const int b = blockIdx.y;
    const int n0 = blockIdx.x * 128;
    const int tid = threadIdx.x;
    const int tx = tid & 15, ty = tid >> 4;
    const float* loc = d_local + (long)b * 64 * 2048;

    if (tid < 64) gin[tid] = d_g1[b * 64 + tid];
    __syncthreads();
    if (tid < 128) {
        float acc = 0.f;
#pragma unroll
        for (int c = 0; c < 64; ++c) acc = fmaf(W3a[tid * 64 + c], gin[c], acc);
        gmid[tid] = fmaxf(fmaf(acc, s3a[tid], b3a[tid]), 0.f);
    }
    __syncthreads();
    if (tid < 128) {
        float acc = 0.f;
#pragma unroll
        for (int c = 0; c < 128; ++c) acc = fmaf(W3b[tid * 128 + c], gmid[c], acc);
        g2s[tid] = fmaxf(fmaf(acc, s3b[tid], b3b[tid]), 0.f);
    }
    __syncthreads();
    {
        int o = tid;
        float acc = bias4a[o];
#pragma unroll
        for (int c = 0; c < 128; ++c)
            acc = fmaf(W4a[o * 192 + 64 + c], g2s[c], acc);
        sgb[o] = acc;
    }

    for (int idx = tid; idx < 16384; idx += 256)
        As[idx] = d_W4a_t[idx];
    for (int idx = tid; idx < 2048; idx += 256) {
        int k = idx >> 5, q4 = (idx & 31) * 4;
        *(float4*)&Bs[k * 128 + q4] = *(const float4*)&loc[k * 2048 + n0 + q4];
    }
    for (int idx = tid; idx < 768; idx += 256) sw[idx] = W4b[idx];
    __syncthreads();

    float p[3][8];
#pragma unroll
    for (int q = 0; q < 3; ++q)
#pragma unroll
        for (int j = 0; j < 8; ++j) p[q][j] = 0.f;

#pragma unroll
    for (int pass = 0; pass < 2; ++pass) {
        float acc[8][8];
#pragma unroll
        for (int i = 0; i < 8; ++i)
#pragma unroll
            for (int j = 0; j < 8; ++j) acc[i][j] = 0.f;
#pragma unroll 4
        for (int k = 0; k < 64; ++k) {
            float a[8], bb[8];
            *(float4*)&a[0] = *(const float4*)&As[k * 256 + pass * 128 + ty * 8];
            *(float4*)&a[4] = *(const float4*)&As[k * 256 + pass * 128 + ty * 8 + 4];
            *(float4*)&bb[0] = *(const float4*)&Bs[k * 128 + tx * 8];
            *(float4*)&bb[4] = *(const float4*)&Bs[k * 128 + tx * 8 + 4];
#pragma unroll
            for (int i = 0; i < 8; ++i)
#pragma unroll
                for (int j = 0; j < 8; ++j)
                    acc[i][j] = fmaf(a[i], bb[j], acc[i][j]);
        }
#pragma unroll
        for (int i = 0; i < 8; ++i) {
            int o = pass * 128 + ty * 8 + i;
            float g = sgb[o];
            float w0 = sw[o], w1 = sw[256 + o], w2 = sw[512 + o];
#pragma unroll
            for (int j = 0; j < 8; ++j) {
                float r = fmaxf(acc[i][j] + g, 0.f);
                p[0][j] = fmaf(w0, r, p[0][j]);
                p[1][j] = fmaf(w1, r, p[1][j]);
                p[2][j] = fmaf(w2, r, p[2][j]);
            }
        }
    }

#pragma unroll
    for (int q = 0; q < 3; ++q)
#pragma unroll
        for (int j = 0; j < 8; ++j)
            po[(ty * 3 + q) * 128 + tx * 8 + j] = p[q][j];
    __syncthreads();

    for (int item = tid; item < 384; item += 256) {
        int q = item >> 7, nn = item & 127;
        float s = bias4b[q];
#pragma unroll
        for (int t = 0; t < 16; ++t)
            s += po[(t * 3 + q) * 128 + nn];
        out[((long)b * 3 + q) * 2048 + n0 + nn] = s;
    }
}

// ---------------- host launcher ----------------
extern "C" void kernel_launch(void* const* d_in, const int* in_sizes, int n_in,
                              void* d_out, int out_size)
{
    const float* x      = (const float*)d_in[0];
    const float* W_dup  = (const float*)d_in[1];
    const float* s_dup  = (const float*)d_in[2];
    const float* b_dup  = (const float*)d_in[3];
    const float* W_c1   = (const float*)d_in[4];
    const float* s_c1   = (const float*)d_in[5];
    const float* b_c1   = (const float*)d_in[6];
    const float* W2a    = (const float*)d_in[7];
    const float* s2a    = (const float*)d_in[8];
    const float* b2a    = (const float*)d_in[9];
    const float* W2b    = (const float*)d_in[10];
    const float* s2b    = (const float*)d_in[11];
    const float* b2b    = (const float*)d_in[12];
    const float* W2c    = (const float*)d_in[13];
    const float* s2c    = (const float*)d_in[14];
    const float* b2c    = (const float*)d_in[15];
    const float* W3a    = (const float*)d_in[16];
    const float* s3a    = (const float*)d_in[17];
    const float* b3a    = (const float*)d_in[18];
    const float* W3b    = (const float*)d_in[19];
    const float* s3b    = (const float*)d_in[20];
    const float* b3b    = (const float*)d_in[21];
    const float* W4a    = (const float*)d_in[22];
    const float* bias4a = (const float*)d_in[23];
    const float* W4b    = (const float*)d_in[24];
    const float* bias4b = (const float*)d_in[25];

    float *p_h1, *p_h2, *p_wpack;
    cudaGetSymbolAddress((void**)&p_h1, d_h1);
    cudaGetSymbolAddress((void**)&p_h2, d_h2);
    cudaGetSymbolAddress((void**)&p_wpack, d_wpack);

    static int attr_set = 0;
    if (!attr_set) {
        cudaFuncSetAttribute(sym_pair,
                             cudaFuncAttributeMaxDynamicSharedMemorySize, 67072);
        cudaFuncSetAttribute(megaconv,
                             cudaFuncAttributeMaxDynamicSharedMemorySize, 74240);
        cudaFuncSetAttribute(head_out,
                             cudaFuncAttributeMaxDynamicSharedMemorySize, 128768);
        attr_set = 1;
    }

    prep_weights<<<114, 256>>>(W4a, W2a, W2b, W2c);
    // move packed conv weights into constant bank (graph-capturable D2D copy)
    cudaMemcpyToSymbolAsync(c_w, p_wpack, 4 * 4096 * sizeof(float), 0,
                            cudaMemcpyDeviceToDevice, 0);
    // L1: (256x128) @ x[b](128x1024) -> h1
    gemmA<<<dim3(8, 2, 8), 256>>>(W_dup, x, p_h1, s_dup, b_dup,
                                  128, 1024, 131072L, 262144L);
    // L2: (64x128) @ h1[b] as (128x2048) -> h2, + fused xx/gmax
    gemmL2<<<dim3(16, 1, 8), 256>>>(W_c1, p_h1, p_h2, s_c1, b_c1,
                                    128, 2048, 262144L, 131072L);
    sym_pair<<<dim3(136, 8), 256, 67072>>>();
    megaconv<<<dim3(64, 8), 256, 74240>>>(s2a, b2a, s2b, b2b, s2c, b2c);
    head_out<<<dim3(16, 8), 256, 128768>>>(W3a, s3a, b3a, W3b, s3b, b3b,
                                           W4a, bias4a, W4b, bias4b,
                                           (float*)d_out);
}

// round 16
// speedup vs baseline: 1.0201x; 1.0201x over previous
#include <cuda_runtime.h>
#include <cstdint>

// ---------------- scratch (static device globals; no allocation) ----------------
__device__ float d_h1[8 * 256 * 1024];      // after dup conv  (8MB)
__device__ float d_h2[8 * 64 * 2048];       // after c1 conv   (4MB)
__device__ float d_xx[8 * 2048];            // per-point squared norms
__device__ float d_g1[8 * 64];              // global max feature (int-atomic bits)
__device__ float d_local[8 * 64 * 2048];    // max over k        (4MB)
__device__ float d_W4a_t[64 * 256];         // W4a[:,0:64] transposed [k][o]
__device__ float d_W2a_nb_t[64 * 64];       // W2a[:,0:64]  as [c][o]
__device__ float d_W2a_diff_t[64 * 64];     // (W2a[:,64:128]-W2a[:,0:64]) as [c][o]
__device__ float d_W2b_t[64 * 64];          // W2b as [c][o]
__device__ float d_W2c_t[64 * 64];          // W2c as [c][o]
// symmetric-pairwise partial top-4: [b][rowblk][otherblk][row128][4]
__device__ float d_pv[8 * 16 * 16 * 128 * 4];   // 8MB
__device__ int   d_pi[8 * 16 * 16 * 128 * 4];   // 8MB

// ---------------- weight repack + g1 reset ----------------
__global__ void prep_weights(const float* __restrict__ W4a,
                             const float* __restrict__ W2a,
                             const float* __restrict__ W2b,
                             const float* __restrict__ W2c)
{
    int t = blockIdx.x * blockDim.x + threadIdx.x;
    if (t < 16384) {
        int k = t >> 8, o = t & 255;
        d_W4a_t[t] = W4a[o * 192 + k];
    } else if (t < 20480) {
        int i = t - 16384;
        int c = i >> 6, o = i & 63;
        float w0 = W2a[o * 128 + c];
        d_W2a_nb_t[i]   = w0;
        d_W2a_diff_t[i] = W2a[o * 128 + 64 + c] - w0;
    } else if (t < 24576) {
        int i = t - 20480;
        int c = i >> 6, o = i & 63;
        d_W2b_t[i] = W2b[o * 64 + c];
    } else if (t < 28672) {
        int i = t - 24576;
        int c = i >> 6, o = i & 63;
        d_W2c_t[i] = W2c[o * 64 + c];
    } else if (t < 29184) {
        d_g1[t - 28672] = 0.0f;
    }
}

// =====================================================================
// GEMM A: 128(O) x 128(N) tile, 256 threads, 8x8 micro-tile, Ktile 16.
// =====================================================================
__global__ void __launch_bounds__(256) gemmA(
    const float* __restrict__ A, const float* __restrict__ B, float* __restrict__ C,
    const float* __restrict__ scale, const float* __restrict__ bias,
    int K, int N, long sB, long sC)
{
    __shared__ float As[16][128];
    __shared__ float Bs[16][128];
    const float* Bp = B + (long)blockIdx.z * sB;
    float* Cp = C + (long)blockIdx.z * sC;
    const int o0 = blockIdx.y * 128;
    const int n0 = blockIdx.x * 128;
    const int tid = threadIdx.x;
    const int tx = tid & 15, ty = tid >> 4;

    const int ar = tid >> 1;
    const int aq = (tid & 1) * 8;
    const int bk = tid >> 4;
    const int bn = (tid & 15) * 8;

    float acc[8][8];
#pragma unroll
    for (int i = 0; i < 8; ++i)
#pragma unroll
        for (int j = 0; j < 8; ++j) acc[i][j] = 0.f;

    for (int k0 = 0; k0 < K; k0 += 16) {
        float4 a0 = *(const float4*)&A[(long)(o0 + ar) * K + k0 + aq];
        float4 a1 = *(const float4*)&A[(long)(o0 + ar) * K + k0 + aq + 4];
        As[aq + 0][ar] = a0.x; As[aq + 1][ar] = a0.y;
        As[aq + 2][ar] = a0.z; As[aq + 3][ar] = a0.w;
        As[aq + 4][ar] = a1.x; As[aq + 5][ar] = a1.y;
        As[aq + 6][ar] = a1.z; As[aq + 7][ar] = a1.w;
        *(float4*)&Bs[bk][bn]     = *(const float4*)&Bp[(long)(k0 + bk) * N + n0 + bn];
        *(float4*)&Bs[bk][bn + 4] = *(const float4*)&Bp[(long)(k0 + bk) * N + n0 + bn + 4];
        __syncthreads();
#pragma unroll 4
        for (int k = 0; k < 16; ++k) {
            float a[8], b[8];
            *(float4*)&a[0] = *(const float4*)&As[k][ty * 8];
            *(float4*)&a[4] = *(const float4*)&As[k][ty * 8 + 4];
            *(float4*)&b[0] = *(const float4*)&Bs[k][tx * 8];
            *(float4*)&b[4] = *(const float4*)&Bs[k][tx * 8 + 4];
#pragma unroll
            for (int i = 0; i < 8; ++i)
#pragma unroll
                for (int j = 0; j < 8; ++j)
                    acc[i][j] = fmaf(a[i], b[j], acc[i][j]);
        }
        __syncthreads();
    }

#pragma unroll
    for (int i = 0; i < 8; ++i) {
        int o = o0 + ty * 8 + i;
        float sv = scale[o];
        float bv = bias[o];
        float r[8];
#pragma unroll
        for (int j = 0; j < 8; ++j)
            r[j] = fmaxf(fmaf(acc[i][j], sv, bv), 0.f);
        *(float4*)&Cp[(long)o * N + n0 + tx * 8]     = *(float4*)&r[0];
        *(float4*)&Cp[(long)o * N + n0 + tx * 8 + 4] = *(float4*)&r[4];
    }
}

// =====================================================================
// GEMM L2: 64(O) x 128(N) tile, 256 threads, 8x4 micro-tile, Ktile 16.
// grid (16,1,8) = 128 CTAs. Fused xx + gmax.
// =====================================================================
__global__ void __launch_bounds__(256) gemmL2(
    const float* __restrict__ A, const float* __restrict__ B, float* __restrict__ C,
    const float* __restrict__ scale, const float* __restrict__ bias,
    int K, int N, long sB, long sC)
{
    __shared__ float As[16][64];
    __shared__ float Bs[16][128];
    __shared__ float ps[8 * 128];      // xx partials [ty][col]
    __shared__ float pm[64 * 32];      // gmax partials [o][tx]
    const int b = blockIdx.z;
    const float* Bp = B + (long)b * sB;
    float* Cp = C + (long)b * sC;
    const int n0 = blockIdx.x * 128;
    const int tid = threadIdx.x;
    const int tx = tid & 31, ty = tid >> 5;

    const int ar = tid >> 2;
    const int aq = (tid & 3) * 4;
    const int bk = tid >> 4;
    const int bn = (tid & 15) * 8;

    float acc[8][4];
#pragma unroll
    for (int i = 0; i < 8; ++i)
#pragma unroll
        for (int j = 0; j < 4; ++j) acc[i][j] = 0.f;

    for (int k0 = 0; k0 < K; k0 += 16) {
        float4 a0 = *(const float4*)&A[(long)ar * K + k0 + aq];
        As[aq + 0][ar] = a0.x; As[aq + 1][ar] = a0.y;
        As[aq + 2][ar] = a0.z; As[aq + 3][ar] = a0.w;
        *(float4*)&Bs[bk][bn]     = *(const float4*)&Bp[(long)(k0 + bk) * N + n0 + bn];
        *(float4*)&Bs[bk][bn + 4] = *(const float4*)&Bp[(long)(k0 + bk) * N + n0 + bn + 4];
        __syncthreads();
#pragma unroll 4
        for (int k = 0; k < 16; ++k) {
            float a[8], bb[4];
            *(float4*)&a[0] = *(const float4*)&As[k][ty * 8];
            *(float4*)&a[4] = *(const float4*)&As[k][ty * 8 + 4];
            *(float4*)&bb[0] = *(const float4*)&Bs[k][tx * 4];
#pragma unroll
            for (int i = 0; i < 8; ++i)
#pragma unroll
                for (int j = 0; j < 4; ++j)
                    acc[i][j] = fmaf(a[i], bb[j], acc[i][j]);
        }
        __syncthreads();
    }

    float px[4];
#pragma unroll
    for (int j = 0; j < 4; ++j) px[j] = 0.f;

#pragma unroll
    for (int i = 0; i < 8; ++i) {
        int o = ty * 8 + i;
        float sv = scale[o];
        float bv = bias[o];
        float r[4];
        float gm = 0.f;
#pragma unroll
        for (int j = 0; j < 4; ++j) {
            r[j] = fmaxf(fmaf(acc[i][j], sv, bv), 0.f);
            px[j] = fmaf(r[j], r[j], px[j]);
            gm = fmaxf(gm, r[j]);
        }
        pm[o * 32 + tx] = gm;
        *(float4*)&Cp[(long)o * N + n0 + tx * 4] = *(float4*)&r[0];
    }
#pragma unroll
    for (int j = 0; j < 4; ++j)
        ps[ty * 128 + tx * 4 + j] = px[j];
    __syncthreads();

    if (tid < 128) {
        float s = 0.f;
#pragma unroll
        for (int t = 0; t < 8; ++t) s += ps[t * 128 + tid];
        d_xx[b * 2048 + n0 + tid] = s;
    }
    if (tid < 64) {
        float m = 0.f;
#pragma unroll
        for (int t = 0; t < 32; ++t) m = fmaxf(m, pm[tid * 32 + t]);
        atomicMax((int*)&d_g1[b * 64 + tid], __float_as_int(m));
    }
}

// ---------------- top-4 inserts ----------------
__device__ __forceinline__ void ins4(float v, int m, float* V, int* I)
{
#pragma unroll
    for (int s = 0; s < 4; ++s) {
        if (v > V[s]) {
            float tv = V[s]; V[s] = v; v = tv;
            int   tm = I[s]; I[s] = m; m = tm;
        }
    }
}
__device__ __forceinline__ void ins4t(float v, int m, float* V, int* I)
{
#pragma unroll
    for (int s = 0; s < 4; ++s) {
        bool better = (v > V[s]) || (v == V[s] && m < I[s]);
        if (better) {
            float tv = V[s]; V[s] = v; v = tv;
            int   tm = I[s]; I[s] = m; m = tm;
        }
    }
}

// =====================================================================
// symmetric pairwise (R12-proven, measured 104 us). grid (136,8), 256 thr.
// =====================================================================
__global__ void __launch_bounds__(256) sym_pair()
{
    extern __shared__ float sm[];
    float* smI   = sm;                 // [64][128] phase 1
    float* smJ   = sm + 8192;          // [64][128] phase 1
    float* score = sm;                 // [128][129] phase 2 (aliases operands)
    float* sxxI  = sm + 16512;         // [128]
    float* sxxJ  = sm + 16640;         // [128]

    int I = 0, J = 0;
    {
        int rem = blockIdx.x;
#pragma unroll
        for (int i = 0; i < 16; ++i) {
            int cnt = 16 - i;
            if (rem < cnt) { I = i; J = i + rem; break; }
            rem -= cnt;
        }
    }
    const int b = blockIdx.y;
    const int tid = threadIdx.x;
    const int nI = I * 128, nJ = J * 128;
    const float* h = d_h2 + (long)b * 64 * 2048;

    for (int idx = tid; idx < 2048; idx += 256) {
        int c = idx >> 5, q4 = (idx & 31) * 4;
        *(float4*)&smI[c * 128 + q4] = *(const float4*)&h[c * 2048 + nI + q4];
        *(float4*)&smJ[c * 128 + q4] = *(const float4*)&h[c * 2048 + nJ + q4];
    }
    if (tid < 128) {
        sxxI[tid] = d_xx[b * 2048 + nI + tid];
        sxxJ[tid] = d_xx[b * 2048 + nJ + tid];
    }
    __syncthreads();

    const int tx = tid & 15, ty = tid >> 4;
    float acc[8][8];
#pragma unroll
    for (int i = 0; i < 8; ++i)
#pragma unroll
        for (int j = 0; j < 8; ++j) acc[i][j] = 0.f;

#pragma unroll 4
    for (int k = 0; k < 64; ++k) {
        float a[8], bb[8];
        *(float4*)&a[0] = *(const float4*)&smI[k * 128 + ty * 8];
        *(float4*)&a[4] = *(const float4*)&smI[k * 128 + ty * 8 + 4];
        *(float4*)&bb[0] = *(const float4*)&smJ[k * 128 + tx * 8];
        *(float4*)&bb[4] = *(const float4*)&smJ[k * 128 + tx * 8 + 4];
#pragma unroll
        for (int i = 0; i < 8; ++i)
#pragma unroll
            for (int j = 0; j < 8; ++j)
                acc[i][j] = fmaf(a[i], bb[j], acc[i][j]);
    }
    __syncthreads();   // operands dead; score may overwrite

#pragma unroll
    for (int i = 0; i < 8; ++i)
#pragma unroll
        for (int j = 0; j < 8; ++j)
            score[(ty * 8 + i) * 129 + tx * 8 + j] = acc[i][j];
    __syncthreads();

    if (tid < 128) {
        float V[4] = {-1e30f, -1e30f, -1e30f, -1e30f};
        int   Ix[4] = {0, 0, 0, 0};
        const float* srow = &score[tid * 129];
#pragma unroll 4
        for (int m = 0; m < 128; ++m) {
            float s = fmaf(2.0f, srow[m], -sxxJ[m]);
            if (s > V[3]) ins4(s, nJ + m, V, Ix);
        }
        long base = ((((long)b * 16 + I) * 16 + J) * 128 + tid) * 4;
        *(float4*)&d_pv[base] = make_float4(V[0], V[1], V[2], V[3]);
        *(int4*)&d_pi[base] = make_int4(Ix[0], Ix[1], Ix[2], Ix[3]);
    } else if (I < J) {
        int m = tid - 128;
        float V[4] = {-1e30f, -1e30f, -1e30f, -1e30f};
        int   Ix[4] = {0, 0, 0, 0};
#pragma unroll 4
        for (int rr = 0; rr < 128; ++rr) {
            float s = fmaf(2.0f, score[rr * 129 + m], -sxxI[rr]);
            if (s > V[3]) ins4(s, nI + rr, V, Ix);
        }
        long base = ((((long)b * 16 + J) * 16 + I) * 128 + m) * 4;
        *(float4*)&d_pv[base] = make_float4(V[0], V[1], V[2], V[3]);
        *(int4*)&d_pi[base] = make_int4(Ix[0], Ix[1], Ix[2], Ix[3]);
    }
}

// =====================================================================
// mega-fused edge convs v3: weights via __ldg from global (warp-uniform
// broadcast, L1-resident), smem 74.2KB -> 3 CTAs/SM. Phases: merge+ctr ->
// gather -> GEMM1(+diff) -> GEMM2 -> GEMM3(+kmax). grid (64,8), 256 thr.
// smem floats: ping 8192 | pong 8192 | ctr 2048 | sidx 128 = 18560
// =====================================================================
__global__ void __launch_bounds__(256, 3) megaconv(
    const float* __restrict__ s2a, const float* __restrict__ b2a,
    const float* __restrict__ s2b, const float* __restrict__ b2b,
    const float* __restrict__ s2c, const float* __restrict__ b2c)
{
    extern __shared__ float sm[];
    float* ping  = sm;
    float* pong  = sm + 8192;
    float* ctr   = sm + 16384;
    int*   sidx  = (int*)(sm + 18432);

    const int b = blockIdx.y;
    const int n0p = blockIdx.x * 32;
    const int tid = threadIdx.x;
    const int tx = tid & 31, ty = tid >> 5;
    const float* h = d_h2 + (long)b * 64 * 2048;

    if (tid < 32) {
        int row = n0p + tid;
        int rb = row >> 7, rl = row & 127;
        long pbase = ((((long)b * 16 + rb) * 16) * 128 + rl) * 4;
        float V[4] = {-1e30f, -1e30f, -1e30f, -1e30f};
        int   I[4] = {0, 0, 0, 0};
#pragma unroll
        for (int o = 0; o < 16; ++o) {
            float4 v = *(const float4*)&d_pv[pbase + (long)o * 512];
            int4  ix = *(const int4*)&d_pi[pbase + (long)o * 512];
            ins4t(v.x, ix.x, V, I);
            ins4t(v.y, ix.y, V, I);
            ins4t(v.z, ix.z, V, I);
            ins4t(v.w, ix.w, V, I);
        }
        sidx[tid * 4 + 0] = I[0];
        sidx[tid * 4 + 1] = I[1];
        sidx[tid * 4 + 2] = I[2];
        sidx[tid * 4 + 3] = I[3];
    } else {
        int t = tid - 32;
        for (int i = t; i < 512; i += 224) {
            int c = i >> 3, q4 = (i & 7) * 4;
            *(float4*)&ctr[c * 32 + q4] = *(const float4*)&h[c * 2048 + n0p + q4];
        }
    }
    __syncthreads();

#pragma unroll 4
    for (int e = tid; e < 8192; e += 256) {
        int c = e >> 7, j = e & 127;
        ping[e] = h[c * 2048 + sidx[j]];
    }
    __syncthreads();

    float acc[8][4];
    const int wrow = ty * 8;   // warp-uniform weight row offset

    // ---- GEMM1: W2a_nb @ feat (+ diff term) -> pong ----
#pragma unroll
    for (int i = 0; i < 8; ++i)
#pragma unroll
        for (int j = 0; j < 4; ++j) acc[i][j] = 0.f;
#pragma unroll 4
    for (int k = 0; k < 64; ++k) {
        float a[8], bb[4];
        *(float4*)&a[0] = __ldg((const float4*)&d_W2a_nb_t[k * 64 + wrow]);
        *(float4*)&a[4] = __ldg((const float4*)&d_W2a_nb_t[k * 64 + wrow + 4]);
        *(float4*)&bb[0] = *(const float4*)&ping[k * 128 + tx * 4];
#pragma unroll
        for (int i = 0; i < 8; ++i)
#pragma unroll
            for (int j = 0; j < 4; ++j)
                acc[i][j] = fmaf(a[i], bb[j], acc[i][j]);
    }
    {
        float diffv[8];
#pragma unroll
        for (int i = 0; i < 8; ++i) diffv[i] = 0.f;
#pragma unroll 4
        for (int c = 0; c < 64; ++c) {
            float a[8];
            *(float4*)&a[0] = __ldg((const float4*)&d_W2a_diff_t[c * 64 + wrow]);
            *(float4*)&a[4] = __ldg((const float4*)&d_W2a_diff_t[c * 64 + wrow + 4]);
            float cv = ctr[c * 32 + tx];
#pragma unroll
            for (int i = 0; i < 8; ++i)
                diffv[i] = fmaf(a[i], cv, diffv[i]);
        }
#pragma unroll
        for (int i = 0; i < 8; ++i) {
            int o = wrow + i;
            float sv = s2a[o], bv = b2a[o];
            float r[4];
#pragma unroll
            for (int j = 0; j < 4; ++j)
                r[j] = fmaxf(fmaf(acc[i][j] + diffv[i], sv, bv), 0.f);
            *(float4*)&pong[o * 128 + tx * 4] = *(float4*)&r[0];
        }
    }
    __syncthreads();

    // ---- GEMM2: W2b @ fa -> ping ----
#pragma unroll
    for (int i = 0; i < 8; ++i)
#pragma unroll
        for (int j = 0; j < 4; ++j) acc[i][j] = 0.f;
#pragma unroll 4
    for (int k = 0; k < 64; ++k) {
        float a[8], bb[4];
        *(float4*)&a[0] = __ldg((const float4*)&d_W2b_t[k * 64 + wrow]);
        *(float4*)&a[4] = __ldg((const float4*)&d_W2b_t[k * 64 + wrow + 4]);
        *(float4*)&bb[0] = *(const float4*)&pong[k * 128 + tx * 4];
#pragma unroll
        for (int i = 0; i < 8; ++i)
#pragma unroll
            for (int j = 0; j < 4; ++j)
                acc[i][j] = fmaf(a[i], bb[j], acc[i][j]);
    }
#pragma unroll
    for (int i = 0; i < 8; ++i) {
        int o = wrow + i;
        float sv = s2b[o], bv = b2b[o];
        float r[4];
#pragma unroll
        for (int j = 0; j < 4; ++j)
            r[j] = fmaxf(fmaf(acc[i][j], sv, bv), 0.f);
        *(float4*)&ping[o * 128 + tx * 4] = *(float4*)&r[0];
    }
    __syncthreads();

    // ---- GEMM3: W2c @ fb -> kmax -> d_local ----
#pragma unroll
    for (int i = 0; i < 8; ++i)
#pragma unroll
        for (int j = 0; j < 4; ++j) acc[i][j] = 0.f;
#pragma unroll 4
    for (int k = 0; k < 64; ++k) {
        float a[8], bb[4];
        *(float4*)&a[0] = __ldg((const float4*)&d_W2c_t[k * 64 + wrow]);
        *(float4*)&a[4] = __ldg((const float4*)&d_W2c_t[k * 64 + wrow + 4]);
        *(float4*)&bb[0] = *(const float4*)&ping[k * 128 + tx * 4];
#pragma unroll
        for (int i = 0; i < 8; ++i)
#pragma unroll
            for (int j = 0; j < 4; ++j)
                acc[i][j] = fmaf(a[i], bb[j], acc[i][j]);
    }
    float* locp = d_local + (long)b * 64 * 2048;
#pragma unroll
    for (int i = 0; i < 8; ++i) {
        int o = wrow + i;
        float sv = s2c[o], bv = b2c[o];
        float r[4];
#pragma unroll
        for (int j = 0; j < 4; ++j)
            r[j] = fmaxf(fmaf(acc[i][j], sv, bv), 0.f);
        locp[(long)o * 2048 + n0p + tx] =
            fmaxf(fmaxf(r[0], r[1]), fmaxf(r[2], r[3]));
    }
}

// =====================================================================
// fused head: inline gpath (g1->g2->gb), h4 = relu(W4a_c@local + gb),
// out = W4b @ h4 + bias4b.  grid (16, 8), block 256.
// =====================================================================
__global__ void __launch_bounds__(256) head_out(
    const float* __restrict__ W3a, const float* __restrict__ s3a,
    const float* __restrict__ b3a, const float* __restrict__ W3b,
    const float* __restrict__ s3b, const float* __restrict__ b3b,
    const float* __restrict__ W4a, const float* __restrict__ bias4a,
    const float* __restrict__ W4b, const float* __restrict__ bias4b,
    float* __restrict__ out)
{
    extern __shared__ float smem[];
    float* As   = smem;                 // [64][256]
    float* Bs   = As + 64 * 256;        // [64][128]
    float* po   = Bs + 64 * 128;        // [16][3][128]
    float* sgb  = po + 16 * 3 * 128;    // [256]
    float* sw   = sgb + 256;            // [3][256]
    float* gin  = sw + 768;             // [64]
    float* gmid = gin + 64;             // [128]
    float* g2s  = gmid + 128;           // [128]

    const int b = blockIdx.y;
    const int n0 = blockIdx.x * 128;
    const int tid = threadIdx.x;
    const int tx = tid & 15, ty = tid >> 4;
    const float* loc = d_local + (long)b * 64 * 2048;

    if (tid < 64) gin[tid] = d_g1[b * 64 + tid];
    __syncthreads();
    if (tid < 128) {
        float acc = 0.f;
#pragma unroll
        for (int c = 0; c < 64; ++c) acc = fmaf(W3a[tid * 64 + c], gin[c], acc);
        gmid[tid] = fmaxf(fmaf(acc, s3a[tid], b3a[tid]), 0.f);
    }
    __syncthreads();
    if (tid < 128) {
        float acc = 0.f;
#pragma unroll
        for (int c = 0; c < 128; ++c) acc = fmaf(W3b[tid * 128 + c], gmid[c], acc);
        g2s[tid] = fmaxf(fmaf(acc, s3b[tid], b3b[tid]), 0.f);
    }
    __syncthreads();
    {
        int o = tid;
        float acc = bias4a[o];
#pragma unroll
        for (int c = 0; c < 128; ++c)
            acc = fmaf(W4a[o * 192 + 64 + c], g2s[c], acc);
        sgb[o] = acc;
    }

    for (int idx = tid; idx < 16384; idx += 256)
        As[idx] = d_W4a_t[idx];
    for (int idx = tid; idx < 2048; idx += 256) {
        int k = idx >> 5, q4 = (idx & 31) * 4;
        *(float4*)&Bs[k * 128 + q4] = *(const float4*)&loc[k * 2048 + n0 + q4];
    }
    for (int idx = tid; idx < 768; idx += 256) sw[idx] = W4b[idx];
    __syncthreads();

    float p[3][8];
#pragma unroll
    for (int q = 0; q < 3; ++q)
#pragma unroll
        for (int j = 0; j < 8; ++j) p[q][j] = 0.f;

#pragma unroll
    for (int pass = 0; pass < 2; ++pass) {
        float acc[8][8];
#pragma unroll
        for (int i = 0; i < 8; ++i)
#pragma unroll
            for (int j = 0; j < 8; ++j) acc[i][j] = 0.f;
#pragma unroll 4
        for (int k = 0; k < 64; ++k) {
            float a[8], bb[8];
            *(float4*)&a[0] = *(const float4*)&As[k * 256 + pass * 128 + ty * 8];
            *(float4*)&a[4] = *(const float4*)&As[k * 256 + pass * 128 + ty * 8 + 4];
            *(float4*)&bb[0] = *(const float4*)&Bs[k * 128 + tx * 8];
            *(float4*)&bb[4] = *(const float4*)&Bs[k * 128 + tx * 8 + 4];
#pragma unroll
            for (int i = 0; i < 8; ++i)
#pragma unroll
                for (int j = 0; j < 8; ++j)
                    acc[i][j] = fmaf(a[i], bb[j], acc[i][j]);
        }
#pragma unroll
        for (int i = 0; i < 8; ++i) {
            int o = pass * 128 + ty * 8 + i;
            float g = sgb[o];
            float w0 = sw[o], w1 = sw[256 + o], w2 = sw[512 + o];
#pragma unroll
            for (int j = 0; j < 8; ++j) {
                float r = fmaxf(acc[i][j] + g, 0.f);
                p[0][j] = fmaf(w0, r, p[0][j]);
                p[1][j] = fmaf(w1, r, p[1][j]);
                p[2][j] = fmaf(w2, r, p[2][j]);
            }
        }
    }

#pragma unroll
    for (int q = 0; q < 3; ++q)
#pragma unroll
        for (int j = 0; j < 8; ++j)
            po[(ty * 3 + q) * 128 + tx * 8 + j] = p[q][j];
    __syncthreads();

    for (int item = tid; item < 384; item += 256) {
        int q = item >> 7, nn = item & 127;
        float s = bias4b[q];
#pragma unroll
        for (int t = 0; t < 16; ++t)
            s += po[(t * 3 + q) * 128 + nn];
        out[((long)b * 3 + q) * 2048 + n0 + nn] = s;
    }
}

// ---------------- host launcher ----------------
extern "C" void kernel_launch(void* const* d_in, const int* in_sizes, int n_in,
                              void* d_out, int out_size)
{
    const float* x      = (const float*)d_in[0];
    const float* W_dup  = (const float*)d_in[1];
    const float* s_dup  = (const float*)d_in[2];
    const float* b_dup  = (const float*)d_in[3];
    const float* W_c1   = (const float*)d_in[4];
    const float* s_c1   = (const float*)d_in[5];
    const float* b_c1   = (const float*)d_in[6];
    const float* W2a    = (const float*)d_in[7];
    const float* s2a    = (const float*)d_in[8];
    const float* b2a    = (const float*)d_in[9];
    const float* W2b    = (const float*)d_in[10];
    const float* s2b    = (const float*)d_in[11];
    const float* b2b    = (const float*)d_in[12];
    const float* W2c    = (const float*)d_in[13];
    const float* s2c    = (const float*)d_in[14];
    const float* b2c    = (const float*)d_in[15];
    const float* W3a    = (const float*)d_in[16];
    const float* s3a    = (const float*)d_in[17];
    const float* b3a    = (const float*)d_in[18];
    const float* W3b    = (const float*)d_in[19];
    const float* s3b    = (const float*)d_in[20];
    const float* b3b    = (const float*)d_in[21];
    const float* W4a    = (const float*)d_in[22];
    const float* bias4a = (const float*)d_in[23];
    const float* W4b    = (const float*)d_in[24];
    const float* bias4b = (const float*)d_in[25];

    float *p_h1, *p_h2;
    cudaGetSymbolAddress((void**)&p_h1, d_h1);
    cudaGetSymbolAddress((void**)&p_h2, d_h2);

    static int attr_set = 0;
    if (!attr_set) {
        cudaFuncSetAttribute(sym_pair,
                             cudaFuncAttributeMaxDynamicSharedMemorySize, 67072);
        cudaFuncSetAttribute(megaconv,
                             cudaFuncAttributeMaxDynamicSharedMemorySize, 74240);
        cudaFuncSetAttribute(head_out,
                             cudaFuncAttributeMaxDynamicSharedMemorySize, 128768);
        attr_set = 1;
    }

    prep_weights<<<114, 256>>>(W4a, W2a, W2b, W2c);
    // L1: (256x128) @ x[b](128x1024) -> h1
    gemmA<<<dim3(8, 2, 8), 256>>>(W_dup, x, p_h1, s_dup, b_dup,
                                  128, 1024, 131072L, 262144L);
    // L2: (64x128) @ h1[b] as (128x2048) -> h2, + fused xx/gmax
    gemmL2<<<dim3(16, 1, 8), 256>>>(W_c1, p_h1, p_h2, s_c1, b_c1,
                                    128, 2048, 262144L, 131072L);
    sym_pair<<<dim3(136, 8), 256, 67072>>>();
    megaconv<<<dim3(64, 8), 256, 74240>>>(s2a, b2a, s2b, b2b, s2c, b2c);
    head_out<<<dim3(16, 8), 256, 128768>>>(W3a, s3a, b3a, W3b, s3b, b3b,
                                           W4a, bias4a, W4b, bias4b,
                                           (float*)d_out);
}

// round 17
// speedup vs baseline: 1.1804x; 1.1572x over previous
#include <cuda_runtime.h>
#include <cstdint>

// ---------------- scratch (static device globals; no allocation) ----------------
__device__ float d_h1[8 * 256 * 1024];      // after dup conv  (8MB)
__device__ float d_h2[8 * 64 * 2048];       // after c1 conv   (4MB)
__device__ float d_xx[8 * 2048];            // per-point squared norms
__device__ float d_g1[8 * 64];              // global max feature (int-atomic bits)
__device__ float d_local[8 * 64 * 2048];    // max over k        (4MB)
__device__ float d_W4a_t[64 * 256];         // W4a[:,0:64] transposed [k][o]
__device__ float d_W2a_nb_t[64 * 64];       // W2a[:,0:64]  as [c][o]
__device__ float d_W2a_diff_t[64 * 64];     // (W2a[:,64:128]-W2a[:,0:64]) as [c][o]
__device__ float d_W2b_t[64 * 64];          // W2b as [c][o]
__device__ float d_W2c_t[64 * 64];          // W2c as [c][o]
// symmetric-pairwise partial top-4: [b][rowblk][otherblk][row128][4]
__device__ float d_pv[8 * 16 * 16 * 128 * 4];   // 8MB
__device__ int   d_pi[8 * 16 * 16 * 128 * 4];   // 8MB

// ---------------- weight repack + g1 reset ----------------
__global__ void prep_weights(const float* __restrict__ W4a,
                             const float* __restrict__ W2a,
                             const float* __restrict__ W2b,
                             const float* __restrict__ W2c)
{
    int t = blockIdx.x * blockDim.x + threadIdx.x;
    if (t < 16384) {
        int k = t >> 8, o = t & 255;
        d_W4a_t[t] = W4a[o * 192 + k];
    } else if (t < 20480) {
        int i = t - 16384;
        int c = i >> 6, o = i & 63;
        float w0 = W2a[o * 128 + c];
        d_W2a_nb_t[i]   = w0;
        d_W2a_diff_t[i] = W2a[o * 128 + 64 + c] - w0;
    } else if (t < 24576) {
        int i = t - 20480;
        int c = i >> 6, o = i & 63;
        d_W2b_t[i] = W2b[o * 64 + c];
    } else if (t < 28672) {
        int i = t - 24576;
        int c = i >> 6, o = i & 63;
        d_W2c_t[i] = W2c[o * 64 + c];
    } else if (t < 29184) {
        d_g1[t - 28672] = 0.0f;
    }
}

// =====================================================================
// GEMM A: 128(O) x 128(N) tile, 256 threads, 8x8 micro-tile, Ktile 16.
// =====================================================================
__global__ void __launch_bounds__(256) gemmA(
    const float* __restrict__ A, const float* __restrict__ B, float* __restrict__ C,
    const float* __restrict__ scale, const float* __restrict__ bias,
    int K, int N, long sB, long sC)
{
    __shared__ float As[16][128];
    __shared__ float Bs[16][128];
    const float* Bp = B + (long)blockIdx.z * sB;
    float* Cp = C + (long)blockIdx.z * sC;
    const int o0 = blockIdx.y * 128;
    const int n0 = blockIdx.x * 128;
    const int tid = threadIdx.x;
    const int tx = tid & 15, ty = tid >> 4;

    const int ar = tid >> 1;
    const int aq = (tid & 1) * 8;
    const int bk = tid >> 4;
    const int bn = (tid & 15) * 8;

    float acc[8][8];
#pragma unroll
    for (int i = 0; i < 8; ++i)
#pragma unroll
        for (int j = 0; j < 8; ++j) acc[i][j] = 0.f;

    for (int k0 = 0; k0 < K; k0 += 16) {
        float4 a0 = *(const float4*)&A[(long)(o0 + ar) * K + k0 + aq];
        float4 a1 = *(const float4*)&A[(long)(o0 + ar) * K + k0 + aq + 4];
        As[aq + 0][ar] = a0.x; As[aq + 1][ar] = a0.y;
        As[aq + 2][ar] = a0.z; As[aq + 3][ar] = a0.w;
        As[aq + 4][ar] = a1.x; As[aq + 5][ar] = a1.y;
        As[aq + 6][ar] = a1.z; As[aq + 7][ar] = a1.w;
        *(float4*)&Bs[bk][bn]     = *(const float4*)&Bp[(long)(k0 + bk) * N + n0 + bn];
        *(float4*)&Bs[bk][bn + 4] = *(const float4*)&Bp[(long)(k0 + bk) * N + n0 + bn + 4];
        __syncthreads();
#pragma unroll 4
        for (int k = 0; k < 16; ++k) {
            float a[8], b[8];
            *(float4*)&a[0] = *(const float4*)&As[k][ty * 8];
            *(float4*)&a[4] = *(const float4*)&As[k][ty * 8 + 4];
            *(float4*)&b[0] = *(const float4*)&Bs[k][tx * 8];
            *(float4*)&b[4] = *(const float4*)&Bs[k][tx * 8 + 4];
#pragma unroll
            for (int i = 0; i < 8; ++i)
#pragma unroll
                for (int j = 0; j < 8; ++j)
                    acc[i][j] = fmaf(a[i], b[j], acc[i][j]);
        }
        __syncthreads();
    }

#pragma unroll
    for (int i = 0; i < 8; ++i) {
        int o = o0 + ty * 8 + i;
        float sv = scale[o];
        float bv = bias[o];
        float r[8];
#pragma unroll
        for (int j = 0; j < 8; ++j)
            r[j] = fmaxf(fmaf(acc[i][j], sv, bv), 0.f);
        *(float4*)&Cp[(long)o * N + n0 + tx * 8]     = *(float4*)&r[0];
        *(float4*)&Cp[(long)o * N + n0 + tx * 8 + 4] = *(float4*)&r[4];
    }
}

// =====================================================================
// GEMM L2: 64(O) x 128(N) tile, 256 threads, 8x4 micro-tile, Ktile 16.
// grid (16,1,8) = 128 CTAs. Fused xx + gmax.
// =====================================================================
__global__ void __launch_bounds__(256) gemmL2(
    const float* __restrict__ A, const float* __restrict__ B, float* __restrict__ C,
    const float* __restrict__ scale, const float* __restrict__ bias,
    int K, int N, long sB, long sC)
{
    __shared__ float As[16][64];
    __shared__ float Bs[16][128];
    __shared__ float ps[8 * 128];      // xx partials [ty][col]
    __shared__ float pm[64 * 32];      // gmax partials [o][tx]
    const int b = blockIdx.z;
    const float* Bp = B + (long)b * sB;
    float* Cp = C + (long)b * sC;
    const int n0 = blockIdx.x * 128;
    const int tid = threadIdx.x;
    const int tx = tid & 31, ty = tid >> 5;

    const int ar = tid >> 2;
    const int aq = (tid & 3) * 4;
    const int bk = tid >> 4;
    const int bn = (tid & 15) * 8;

    float acc[8][4];
#pragma unroll
    for (int i = 0; i < 8; ++i)
#pragma unroll
        for (int j = 0; j < 4; ++j) acc[i][j] = 0.f;

    for (int k0 = 0; k0 < K; k0 += 16) {
        float4 a0 = *(const float4*)&A[(long)ar * K + k0 + aq];
        As[aq + 0][ar] = a0.x; As[aq + 1][ar] = a0.y;
        As[aq + 2][ar] = a0.z; As[aq + 3][ar] = a0.w;
        *(float4*)&Bs[bk][bn]     = *(const float4*)&Bp[(long)(k0 + bk) * N + n0 + bn];
        *(float4*)&Bs[bk][bn + 4] = *(const float4*)&Bp[(long)(k0 + bk) * N + n0 + bn + 4];
        __syncthreads();
#pragma unroll 4
        for (int k = 0; k < 16; ++k) {
            float a[8], bb[4];
            *(float4*)&a[0] = *(const float4*)&As[k][ty * 8];
            *(float4*)&a[4] = *(const float4*)&As[k][ty * 8 + 4];
            *(float4*)&bb[0] = *(const float4*)&Bs[k][tx * 4];
#pragma unroll
            for (int i = 0; i < 8; ++i)
#pragma unroll
                for (int j = 0; j < 4; ++j)
                    acc[i][j] = fmaf(a[i], bb[j], acc[i][j]);
        }
        __syncthreads();
    }

    float px[4];
#pragma unroll
    for (int j = 0; j < 4; ++j) px[j] = 0.f;

#pragma unroll
    for (int i = 0; i < 8; ++i) {
        int o = ty * 8 + i;
        float sv = scale[o];
        float bv = bias[o];
        float r[4];
        float gm = 0.f;
#pragma unroll
        for (int j = 0; j < 4; ++j) {
            r[j] = fmaxf(fmaf(acc[i][j], sv, bv), 0.f);
            px[j] = fmaf(r[j], r[j], px[j]);
            gm = fmaxf(gm, r[j]);
        }
        pm[o * 32 + tx] = gm;
        *(float4*)&Cp[(long)o * N + n0 + tx * 4] = *(float4*)&r[0];
    }
#pragma unroll
    for (int j = 0; j < 4; ++j)
        ps[ty * 128 + tx * 4 + j] = px[j];
    __syncthreads();

    if (tid < 128) {
        float s = 0.f;
#pragma unroll
        for (int t = 0; t < 8; ++t) s += ps[t * 128 + tid];
        d_xx[b * 2048 + n0 + tid] = s;
    }
    if (tid < 64) {
        float m = 0.f;
#pragma unroll
        for (int t = 0; t < 32; ++t) m = fmaxf(m, pm[tid * 32 + t]);
        atomicMax((int*)&d_g1[b * 64 + tid], __float_as_int(m));
    }
}

// ---------------- top-4 inserts ----------------
__device__ __forceinline__ void ins4(float v, int m, float* V, int* I)
{
#pragma unroll
    for (int s = 0; s < 4; ++s) {
        if (v > V[s]) {
            float tv = V[s]; V[s] = v; v = tv;
            int   tm = I[s]; I[s] = m; m = tm;
        }
    }
}
__device__ __forceinline__ void ins4t(float v, int m, float* V, int* I)
{
#pragma unroll
    for (int s = 0; s < 4; ++s) {
        bool better = (v > V[s]) || (v == V[s] && m < I[s]);
        if (better) {
            float tv = V[s]; V[s] = v; v = tv;
            int   tm = I[s]; I[s] = m; m = tm;
        }
    }
}

// =====================================================================
// symmetric pairwise v4: R12 GEMM phase; scans quad-batched with max-of-4
// prune (insert sequence identical to scalar scans -> bitwise-same idx).
// score row stride 132 (16B-aligned rows). smem 68608 B. grid (136,8),
// block 256.
// =====================================================================
__global__ void __launch_bounds__(256) sym_pair()
{
    extern __shared__ float sm[];
    float* smI   = sm;                 // [64][128] phase 1
    float* smJ   = sm + 8192;          // [64][128] phase 1
    float* score = sm;                 // [128][132] phase 2 (aliases operands)
    float* sxxI  = sm + 16896;         // [128]
    float* sxxJ  = sm + 17024;         // [128]

    int I = 0, J = 0;
    {
        int rem = blockIdx.x;
#pragma unroll
        for (int i = 0; i < 16; ++i) {
            int cnt = 16 - i;
            if (rem < cnt) { I = i; J = i + rem; break; }
            rem -= cnt;
        }
    }
    const int b = blockIdx.y;
    const int tid = threadIdx.x;
    const int nI = I * 128, nJ = J * 128;
    const float* h = d_h2 + (long)b * 64 * 2048;

    for (int idx = tid; idx < 2048; idx += 256) {
        int c = idx >> 5, q4 = (idx & 31) * 4;
        *(float4*)&smI[c * 128 + q4] = *(const float4*)&h[c * 2048 + nI + q4];
        *(float4*)&smJ[c * 128 + q4] = *(const float4*)&h[c * 2048 + nJ + q4];
    }
    if (tid < 128) {
        sxxI[tid] = d_xx[b * 2048 + nI + tid];
        sxxJ[tid] = d_xx[b * 2048 + nJ + tid];
    }
    __syncthreads();

    const int tx = tid & 15, ty = tid >> 4;
    float acc[8][8];
#pragma unroll
    for (int i = 0; i < 8; ++i)
#pragma unroll
        for (int j = 0; j < 8; ++j) acc[i][j] = 0.f;

#pragma unroll 4
    for (int k = 0; k < 64; ++k) {
        float a[8], bb[8];
        *(float4*)&a[0] = *(const float4*)&smI[k * 128 + ty * 8];
        *(float4*)&a[4] = *(const float4*)&smI[k * 128 + ty * 8 + 4];
        *(float4*)&bb[0] = *(const float4*)&smJ[k * 128 + tx * 8];
        *(float4*)&bb[4] = *(const float4*)&smJ[k * 128 + tx * 8 + 4];
#pragma unroll
        for (int i = 0; i < 8; ++i)
#pragma unroll
            for (int j = 0; j < 8; ++j)
                acc[i][j] = fmaf(a[i], bb[j], acc[i][j]);
    }
    __syncthreads();   // operands dead; score may overwrite

#pragma unroll
    for (int i = 0; i < 8; ++i)
#pragma unroll
        for (int j = 0; j < 8; ++j)
            score[(ty * 8 + i) * 132 + tx * 8 + j] = acc[i][j];
    __syncthreads();

    if (tid < 128) {
        // I-side: query nI+tid scans m ascending (neighbors nJ+m)
        float V[4] = {-1e30f, -1e30f, -1e30f, -1e30f};
        int   Ix[4] = {0, 0, 0, 0};
        const float4* srow4 = (const float4*)&score[tid * 132];
        const float4* sxx4  = (const float4*)sxxJ;
#pragma unroll 4
        for (int m4 = 0; m4 < 32; ++m4) {
            float4 d = srow4[m4];
            float4 xv = sxx4[m4];          // uniform across threads: broadcast
            float s0 = fmaf(2.0f, d.x, -xv.x);
            float s1 = fmaf(2.0f, d.y, -xv.y);
            float s2 = fmaf(2.0f, d.z, -xv.z);
            float s3 = fmaf(2.0f, d.w, -xv.w);
            float mx = fmaxf(fmaxf(s0, s1), fmaxf(s2, s3));
            if (mx > V[3]) {
                int m = m4 * 4;
                if (s0 > V[3]) ins4(s0, nJ + m,     V, Ix);
                if (s1 > V[3]) ins4(s1, nJ + m + 1, V, Ix);
                if (s2 > V[3]) ins4(s2, nJ + m + 2, V, Ix);
                if (s3 > V[3]) ins4(s3, nJ + m + 3, V, Ix);
            }
        }
        long base = ((((long)b * 16 + I) * 16 + J) * 128 + tid) * 4;
        *(float4*)&d_pv[base] = make_float4(V[0], V[1], V[2], V[3]);
        *(int4*)&d_pi[base] = make_int4(Ix[0], Ix[1], Ix[2], Ix[3]);
    } else if (I < J) {
        // J-side: query nJ+m scans r ascending (neighbors nI+r)
        int m = tid - 128;
        float V[4] = {-1e30f, -1e30f, -1e30f, -1e30f};
        int   Ix[4] = {0, 0, 0, 0};
#pragma unroll 4
        for (int r4 = 0; r4 < 32; ++r4) {
            int rr = r4 * 4;
            float d0 = score[(rr)     * 132 + m];
            float d1 = score[(rr + 1) * 132 + m];
            float d2 = score[(rr + 2) * 132 + m];
            float d3 = score[(rr + 3) * 132 + m];
            float s0 = fmaf(2.0f, d0, -sxxI[rr]);
            float s1 = fmaf(2.0f, d1, -sxxI[rr + 1]);
            float s2 = fmaf(2.0f, d2, -sxxI[rr + 2]);
            float s3 = fmaf(2.0f, d3, -sxxI[rr + 3]);
            float mx = fmaxf(fmaxf(s0, s1), fmaxf(s2, s3));
            if (mx > V[3]) {
                if (s0 > V[3]) ins4(s0, nI + rr,     V, Ix);
                if (s1 > V[3]) ins4(s1, nI + rr + 1, V, Ix);
                if (s2 > V[3]) ins4(s2, nI + rr + 2, V, Ix);
                if (s3 > V[3]) ins4(s3, nI + rr + 3, V, Ix);
            }
        }
        long base = ((((long)b * 16 + J) * 16 + I) * 128 + m) * 4;
        *(float4*)&d_pv[base] = make_float4(V[0], V[1], V[2], V[3]);
        *(int4*)&d_pi[base] = make_int4(Ix[0], Ix[1], Ix[2], Ix[3]);
    }
}

// =====================================================================
// mega-fused edge convs (R12-proven): inline merge -> gather -> conv2a(+diff)
// -> conv2b -> conv2c(+kmax) -> d_local.  grid (64, 8), block 256.
// =====================================================================
__global__ void __launch_bounds__(256) megaconv(
    const float* __restrict__ s2a, const float* __restrict__ b2a,
    const float* __restrict__ s2b, const float* __restrict__ b2b,
    const float* __restrict__ s2c, const float* __restrict__ b2c)
{
    extern __shared__ float sm[];
    float* ping  = sm;
    float* pong  = sm + 8192;
    float* wbuf0 = sm + 16384;
    float* wbuf1 = sm + 20480;
    float* ctr   = sm + 24576;
    int*   sidx  = (int*)(sm + 26624);

    const int b = blockIdx.y;
    const int n0p = blockIdx.x * 32;
    const int tid = threadIdx.x;
    const int tx = tid & 31, ty = tid >> 5;
    const float* h = d_h2 + (long)b * 64 * 2048;

    if (tid < 32) {
        int row = n0p + tid;
        int rb = row >> 7, rl = row & 127;
        long pbase = ((((long)b * 16 + rb) * 16) * 128 + rl) * 4;
        float V[4] = {-1e30f, -1e30f, -1e30f, -1e30f};
        int   I[4] = {0, 0, 0, 0};
#pragma unroll
        for (int o = 0; o < 16; ++o) {
            float4 v = *(const float4*)&d_pv[pbase + (long)o * 512];
            int4  ix = *(const int4*)&d_pi[pbase + (long)o * 512];
            ins4t(v.x, ix.x, V, I);
            ins4t(v.y, ix.y, V, I);
            ins4t(v.z, ix.z, V, I);
            ins4t(v.w, ix.w, V, I);
        }
        sidx[tid * 4 + 0] = I[0];
        sidx[tid * 4 + 1] = I[1];
        sidx[tid * 4 + 2] = I[2];
        sidx[tid * 4 + 3] = I[3];
    } else {
        int t = tid - 32;
        for (int i = t; i < 512; i += 224) {
            int c = i >> 3, q4 = (i & 7) * 4;
            *(float4*)&ctr[c * 32 + q4] = *(const float4*)&h[c * 2048 + n0p + q4];
        }
        for (int i = t; i < 1024; i += 224) {
            *(float4*)&wbuf0[i * 4] = *(const float4*)&d_W2a_nb_t[i * 4];
            *(float4*)&wbuf1[i * 4] = *(const float4*)&d_W2a_diff_t[i * 4];
        }
    }
    __syncthreads();

#pragma unroll 8
    for (int e = tid; e < 8192; e += 256) {
        int c = e >> 7, j = e & 127;
        ping[e] = h[c * 2048 + sidx[j]];
    }
    __syncthreads();

    float acc[8][4];

    // ---- GEMM1: W2a_nb @ feat (+ diff term) -> pong ----
#pragma unroll
    for (int i = 0; i < 8; ++i)
#pragma unroll
        for (int j = 0; j < 4; ++j) acc[i][j] = 0.f;
#pragma unroll 4
    for (int k = 0; k < 64; ++k) {
        float a[8], bb[4];
        *(float4*)&a[0] = *(const float4*)&wbuf0[k * 64 + ty * 8];
        *(float4*)&a[4] = *(const float4*)&wbuf0[k * 64 + ty * 8 + 4];
        *(float4*)&bb[0] = *(const float4*)&ping[k * 128 + tx * 4];
#pragma unroll
        for (int i = 0; i < 8; ++i)
#pragma unroll
            for (int j = 0; j < 4; ++j)
                acc[i][j] = fmaf(a[i], bb[j], acc[i][j]);
    }
    {
        float diffv[8];
#pragma unroll
        for (int i = 0; i < 8; ++i) diffv[i] = 0.f;
#pragma unroll 4
        for (int c = 0; c < 64; ++c) {
            float a[8];
            *(float4*)&a[0] = *(const float4*)&wbuf1[c * 64 + ty * 8];
            *(float4*)&a[4] = *(const float4*)&wbuf1[c * 64 + ty * 8 + 4];
            float cv = ctr[c * 32 + tx];
#pragma unroll
            for (int i = 0; i < 8; ++i)
                diffv[i] = fmaf(a[i], cv, diffv[i]);
        }
#pragma unroll
        for (int i = 0; i < 8; ++i) {
            int o = ty * 8 + i;
            float sv = s2a[o], bv = b2a[o];
            float r[4];
#pragma unroll
            for (int j = 0; j < 4; ++j)
                r[j] = fmaxf(fmaf(acc[i][j] + diffv[i], sv, bv), 0.f);
            *(float4*)&pong[o * 128 + tx * 4] = *(float4*)&r[0];
        }
    }
    __syncthreads();

    for (int i = tid; i < 1024; i += 256) {
        *(float4*)&wbuf0[i * 4] = *(const float4*)&d_W2b_t[i * 4];
        *(float4*)&wbuf1[i * 4] = *(const float4*)&d_W2c_t[i * 4];
    }
    __syncthreads();

    // ---- GEMM2: W2b @ fa -> ping ----
#pragma unroll
    for (int i = 0; i < 8; ++i)
#pragma unroll
        for (int j = 0; j < 4; ++j) acc[i][j] = 0.f;
#pragma unroll 4
    for (int k = 0; k < 64; ++k) {
        float a[8], bb[4];
        *(float4*)&a[0] = *(const float4*)&wbuf0[k * 64 + ty * 8];
        *(float4*)&a[4] = *(const float4*)&wbuf0[k * 64 + ty * 8 + 4];
        *(float4*)&bb[0] = *(const float4*)&pong[k * 128 + tx * 4];
#pragma unroll
        for (int i = 0; i < 8; ++i)
#pragma unroll
            for (int j = 0; j < 4; ++j)
                acc[i][j] = fmaf(a[i], bb[j], acc[i][j]);
    }
#pragma unroll
    for (int i = 0; i < 8; ++i) {
        int o = ty * 8 + i;
        float sv = s2b[o], bv = b2b[o];
        float r[4];
#pragma unroll
        for (int j = 0; j < 4; ++j)
            r[j] = fmaxf(fmaf(acc[i][j], sv, bv), 0.f);
        *(float4*)&ping[o * 128 + tx * 4] = *(float4*)&r[0];
    }
    __syncthreads();

    // ---- GEMM3: W2c @ fb -> kmax -> d_local ----
#pragma unroll
    for (int i = 0; i < 8; ++i)
#pragma unroll
        for (int j = 0; j < 4; ++j) acc[i][j] = 0.f;
#pragma unroll 4
    for (int k = 0; k < 64; ++k) {
        float a[8], bb[4];
        *(float4*)&a[0] = *(const float4*)&wbuf1[k * 64 + ty * 8];
        *(float4*)&a[4] = *(const float4*)&wbuf1[k * 64 + ty * 8 + 4];
        *(float4*)&bb[0] = *(const float4*)&ping[k * 128 + tx * 4];
#pragma unroll
        for (int i = 0; i < 8; ++i)
#pragma unroll
            for (int j = 0; j < 4; ++j)
                acc[i][j] = fmaf(a[i], bb[j], acc[i][j]);
    }
    float* locp = d_local + (long)b * 64 * 2048;
#pragma unroll
    for (int i = 0; i < 8; ++i) {
        int o = ty * 8 + i;
        float sv = s2c[o], bv = b2c[o];
        float r[4];
#pragma unroll
        for (int j = 0; j < 4; ++j)
            r[j] = fmaxf(fmaf(acc[i][j], sv, bv), 0.f);
        locp[(long)o * 2048 + n0p + tx] =
            fmaxf(fmaxf(r[0], r[1]), fmaxf(r[2], r[3]));
    }
}

// =====================================================================
// fused head: inline gpath (g1->g2->gb), h4 = relu(W4a_c@local + gb),
// out = W4b @ h4 + bias4b.  grid (16, 8), block 256.
// =====================================================================
__global__ void __launch_bounds__(256) head_out(
    const float* __restrict__ W3a, const float* __restrict__ s3a,
    const float* __restrict__ b3a, const float* __restrict__ W3b,
    const float* __restrict__ s3b, const float* __restrict__ b3b,
    const float* __restrict__ W4a, const float* __restrict__ bias4a,
    const float* __restrict__ W4b, const float* __restrict__ bias4b,
    float* __restrict__ out)
{
    extern __shared__ float smem[];
    float* As   = smem;                 // [64][256]
    float* Bs   = As + 64 * 256;        // [64][128]
    float* po   = Bs + 64 * 128;        // [16][3][128]
    float* sgb  = po + 16 * 3 * 128;    // [256]
    float* sw   = sgb + 256;            // [3][256]
    float* gin  = sw + 768;             // [64]
    float* gmid = gin + 64;             // [128]
    float* g2s  = gmid + 128;           // [128]

    const int b = blockIdx.y;
    const int n0 = blockIdx.x * 128;
    const int tid = threadIdx.x;
    const int tx = tid & 15, ty = tid >> 4;
    const float* loc = d_local + (long)b * 64 * 2048;

    if (tid < 64) gin[tid] = d_g1[b * 64 + tid];
    __syncthreads();
    if (tid < 128) {
        float acc = 0.f;
#pragma unroll
        for (int c = 0; c < 64; ++c) acc = fmaf(W3a[tid * 64 + c], gin[c], acc);
        gmid[tid] = fmaxf(fmaf(acc, s3a[tid], b3a[tid]), 0.f);
    }
    __syncthreads();
    if (tid < 128) {
        float acc = 0.f;
#pragma unroll
        for (int c = 0; c < 128; ++c) acc = fmaf(W3b[tid * 128 + c], gmid[c], acc);
        g2s[tid] = fmaxf(fmaf(acc, s3b[tid], b3b[tid]), 0.f);
    }
    __syncthreads();
    {
        int o = tid;
        float acc = bias4a[o];
#pragma unroll
        for (int c = 0; c < 128; ++c)
            acc = fmaf(W4a[o * 192 + 64 + c], g2s[c], acc);
        sgb[o] = acc;
    }

    for (int idx = tid; idx < 16384; idx += 256)
        As[idx] = d_W4a_t[idx];
    for (int idx = tid; idx < 2048; idx += 256) {
        int k = idx >> 5, q4 = (idx & 31) * 4;
        *(float4*)&Bs[k * 128 + q4] = *(const float4*)&loc[k * 2048 + n0 + q4];
    }
    for (int idx = tid; idx < 768; idx += 256) sw[idx] = W4b[idx];
    __syncthreads();

    float p[3][8];
#pragma unroll
    for (int q = 0; q < 3; ++q)
#pragma unroll
        for (int j = 0; j < 8; ++j) p[q][j] = 0.f;

#pragma unroll
    for (int pass = 0; pass < 2; ++pass) {
        float acc[8][8];
#pragma unroll
        for (int i = 0; i < 8; ++i)
#pragma unroll
            for (int j = 0; j < 8; ++j) acc[i][j] = 0.f;
#pragma unroll 4
        for (int k = 0; k < 64; ++k) {
            float a[8], bb[8];
            *(float4*)&a[0] = *(const float4*)&As[k * 256 + pass * 128 + ty * 8];
            *(float4*)&a[4] = *(const float4*)&As[k * 256 + pass * 128 + ty * 8 + 4];
            *(float4*)&bb[0] = *(const float4*)&Bs[k * 128 + tx * 8];
            *(float4*)&bb[4] = *(const float4*)&Bs[k * 128 + tx * 8 + 4];
#pragma unroll
            for (int i = 0; i < 8; ++i)
#pragma unroll
                for (int j = 0; j < 8; ++j)
                    acc[i][j] = fmaf(a[i], bb[j], acc[i][j]);
        }
#pragma unroll
        for (int i = 0; i < 8; ++i) {
            int o = pass * 128 + ty * 8 + i;
            float g = sgb[o];
            float w0 = sw[o], w1 = sw[256 + o], w2 = sw[512 + o];
#pragma unroll
            for (int j = 0; j < 8; ++j) {
                float r = fmaxf(acc[i][j] + g, 0.f);
                p[0][j] = fmaf(w0, r, p[0][j]);
                p[1][j] = fmaf(w1, r, p[1][j]);
                p[2][j] = fmaf(w2, r, p[2][j]);
            }
        }
    }

#pragma unroll
    for (int q = 0; q < 3; ++q)
#pragma unroll
        for (int j = 0; j < 8; ++j)
            po[(ty * 3 + q) * 128 + tx * 8 + j] = p[q][j];
    __syncthreads();

    for (int item = tid; item < 384; item += 256) {
        int q = item >> 7, nn = item & 127;
        float s = bias4b[q];
#pragma unroll
        for (int t = 0; t < 16; ++t)
            s += po[(t * 3 + q) * 128 + nn];
        out[((long)b * 3 + q) * 2048 + n0 + nn] = s;
    }
}

// ---------------- host launcher ----------------
extern "C" void kernel_launch(void* const* d_in, const int* in_sizes, int n_in,
                              void* d_out, int out_size)
{
    const float* x      = (const float*)d_in[0];
    const float* W_dup  = (const float*)d_in[1];
    const float* s_dup  = (const float*)d_in[2];
    const float* b_dup  = (const float*)d_in[3];
    const float* W_c1   = (const float*)d_in[4];
    const float* s_c1   = (const float*)d_in[5];
    const float* b_c1   = (const float*)d_in[6];
    const float* W2a    = (const float*)d_in[7];
    const float* s2a    = (const float*)d_in[8];
    const float* b2a    = (const float*)d_in[9];
    const float* W2b    = (const float*)d_in[10];
    const float* s2b    = (const float*)d_in[11];
    const float* b2b    = (const float*)d_in[12];
    const float* W2c    = (const float*)d_in[13];
    const float* s2c    = (const float*)d_in[14];
    const float* b2c    = (const float*)d_in[15];
    const float* W3a    = (const float*)d_in[16];
    const float* s3a    = (const float*)d_in[17];
    const float* b3a    = (const float*)d_in[18];
    const float* W3b    = (const float*)d_in[19];
    const float* s3b    = (const float*)d_in[20];
    const float* b3b    = (const float*)d_in[21];
    const float* W4a    = (const float*)d_in[22];
    const float* bias4a = (const float*)d_in[23];
    const float* W4b    = (const float*)d_in[24];
    const float* bias4b = (const float*)d_in[25];

    float *p_h1, *p_h2;
    cudaGetSymbolAddress((void**)&p_h1, d_h1);
    cudaGetSymbolAddress((void**)&p_h2, d_h2);

    static int attr_set = 0;
    if (!attr_set) {
        cudaFuncSetAttribute(sym_pair,
                             cudaFuncAttributeMaxDynamicSharedMemorySize, 68608);
        cudaFuncSetAttribute(megaconv,
                             cudaFuncAttributeMaxDynamicSharedMemorySize, 107008);
        cudaFuncSetAttribute(head_out,
                             cudaFuncAttributeMaxDynamicSharedMemorySize, 128768);
        attr_set = 1;
    }

    prep_weights<<<114, 256>>>(W4a, W2a, W2b, W2c);
    // L1: (256x128) @ x[b](128x1024) -> h1
    gemmA<<<dim3(8, 2, 8), 256>>>(W_dup, x, p_h1, s_dup, b_dup,
                                  128, 1024, 131072L, 262144L);
    // L2: (64x128) @ h1[b] as (128x2048) -> h2, + fused xx/gmax
    gemmL2<<<dim3(16, 1, 8), 256>>>(W_c1, p_h1, p_h2, s_c1, b_c1,
                                    128, 2048, 262144L, 131072L);
    sym_pair<<<dim3(136, 8), 256, 68608>>>();
    megaconv<<<dim3(64, 8), 256, 107008>>>(s2a, b2a, s2b, b2b, s2c, b2c);
    head_out<<<dim3(16, 8), 256, 128768>>>(W3a, s3a, b3a, W3b, s3b, b3b,
                                           W4a, bias4a, W4b, bias4b,
                                           (float*)d_out);
}